// round 1
// baseline (speedup 1.0000x reference)
#include <cuda_runtime.h>
#include <cuda_bf16.h>

// Problem constants
#define NB 32            // N
#define MODES 4
#define EYS 192          // EY_SIZE
#define EY_PLANE (EYS*EYS)        // 36864
#define TOTAL 1184       // (N + 2*KNN + 1) * OUT_RES
#define NK (NB*NB)       // 1024

// Scratch: precomputed weights w[k][m] = U * neff*N0/(neff+N0), laid out [k*4+m]
__device__ float g_w[NK * MODES];

__global__ void compute_weights_kernel(const float* __restrict__ U,
                                       const float* __restrict__ neff) {
    int idx = blockIdx.x * blockDim.x + threadIdx.x;
    if (idx < NK * MODES) {
        float nf = neff[idx];
        float eta = nf * 1.5f / (nf + 1.5f);
        g_w[idx] = eta * U[idx];
    }
}

// One warp per (output row r, 32-aligned column tile c0).
// blockDim = (32, 8): 8 warps per block.
// gridDim  = (TOTAL/32 = 37, TOTAL/8 = 148).
__global__ __launch_bounds__(256) void gather_en_kernel(
    const float* __restrict__ Ey,
    float* __restrict__ out)
{
    const int lane = threadIdx.x;
    const int r    = blockIdx.y * 8 + threadIdx.y;   // 0..1183
    const int c0   = blockIdx.x * 32;                // 0..1152, multiple of 32
    const int c    = c0 + lane;

    // Contributing block ranges. floor((v-160)/32) == ceil((v-191)/32).
    int i_lo = (r  - 160) >> 5; if (i_lo < 0) i_lo = 0;
    int i_hi = r  >> 5;         if (i_hi > NB - 1) i_hi = NB - 1;
    // j-range is uniform across the warp (c0 is 32-aligned)
    int j_lo = (c0 - 160) >> 5; if (j_lo < 0) j_lo = 0;
    int j_hi = c0 >> 5;         if (j_hi > NB - 1) j_hi = NB - 1;

    const float4* __restrict__ w4 = reinterpret_cast<const float4*>(g_w);

    float acc = 0.0f;
    for (int i = i_lo; i <= i_hi; ++i) {
        const int x = r - (i << 5);                      // 0..191
        const long irow = (long)(i * NB) * (MODES * EY_PLANE) + (long)x * EYS;
        for (int j = j_lo; j <= j_hi; ++j) {
            const int k = (i << 5) + j;
            const int y = c - (j << 5);                  // lane-contiguous, 0..191
            const float* p = Ey + irow + (long)j * (MODES * EY_PLANE) + y;
            const float4 wv = __ldg(&w4[k]);             // uniform per warp, L1-resident
            float s;
            s  = wv.x * __ldg(p);
            s += wv.y * __ldg(p + EY_PLANE);
            s += wv.z * __ldg(p + 2 * EY_PLANE);
            s += wv.w * __ldg(p + 3 * EY_PLANE);
            acc += s;
        }
    }
    out[(long)r * TOTAL + c] = acc;
}

extern "C" void kernel_launch(void* const* d_in, const int* in_sizes, int n_in,
                              void* d_out, int out_size) {
    // Inputs (metadata order): hs (unused), U, neff, Ey
    const float* U    = (const float*)d_in[1];
    const float* neff = (const float*)d_in[2];
    const float* Ey   = (const float*)d_in[3];
    float* out = (float*)d_out;

    compute_weights_kernel<<<(NK * MODES + 255) / 256, 256>>>(U, neff);

    dim3 block(32, 8);
    dim3 grid(TOTAL / 32, TOTAL / 8);   // (37, 148)
    gather_en_kernel<<<grid, block>>>(Ey, out);
}

// round 2
// speedup vs baseline: 1.1170x; 1.1170x over previous
#include <cuda_runtime.h>
#include <cuda_bf16.h>

// Problem constants
#define NB 32            // N
#define MODES 4
#define EYS 192          // EY_SIZE
#define EY_PLANE (EYS*EYS)          // 36864 floats
#define EY_PLANE4 (EY_PLANE/4)      // 9216 float4
#define TOTAL 1184       // (N + 2*KNN + 1) * OUT_RES
#define NK (NB*NB)       // 1024

// Scratch: precomputed weights w[k][m] = U * neff*N0/(neff+N0), laid out [k*4+m]
__device__ float g_w[NK * MODES];

__global__ void compute_weights_kernel(const float* __restrict__ U,
                                       const float* __restrict__ neff) {
    int idx = blockIdx.x * blockDim.x + threadIdx.x;
    if (idx < NK * MODES) {
        float nf = neff[idx];
        float eta = nf * 1.5f / (nf + 1.5f);
        g_w[idx] = eta * U[idx];
    }
}

// One thread per (row r, 4-column group). Warp covers 128 consecutive columns.
// All Ey accesses are LDG.128, 512B-coalesced per warp, each byte read once chip-wide.
// blockDim = (32, 8); grid = (ceil(1184/128)=10, 1184/8=148).
__global__ __launch_bounds__(256) void gather_en_kernel(
    const float* __restrict__ Ey,
    float* __restrict__ out)
{
    const int lane = threadIdx.x;
    const int r    = blockIdx.y * 8 + threadIdx.y;     // 0..1183, uniform per warp
    const int c    = blockIdx.x * 128 + lane * 4;      // 16B-aligned column
    const bool active = (c < TOTAL);

    // i-range uniform per warp
    int i_lo = (r - 160) >> 5; if (i_lo < 0) i_lo = 0;
    int i_hi = r >> 5;         if (i_hi > NB - 1) i_hi = NB - 1;

    // j-range per lane; floor((c-160)/32) == ceil((c-191)/32) for this grid
    int j_lo = (c - 160) >> 5; if (j_lo < 0) j_lo = 0;
    int j_hi = c >> 5;         if (j_hi > NB - 1) j_hi = NB - 1;
    if (!active) { j_lo = 1; j_hi = 0; }               // no loads for tail lanes

    const float4* __restrict__ w4  = reinterpret_cast<const float4*>(g_w);
    const float4* __restrict__ Ey4 = reinterpret_cast<const float4*>(Ey);

    float4 acc = make_float4(0.f, 0.f, 0.f, 0.f);

    for (int i = i_lo; i <= i_hi; ++i) {
        const int x = r - (i << 5);                    // 0..191
        // float4 offset of (k = i*32, m = 0, row x, col 0)
        const long base_i = (long)(i << 5) * (MODES * EY_PLANE4) + (long)x * (EYS / 4);
        for (int j = j_lo; j <= j_hi; ++j) {
            const int k = (i << 5) + j;
            const int y4 = (c - (j << 5)) >> 2;        // 0..47 float4 within row
            const float4* p = Ey4 + base_i + (long)j * (MODES * EY_PLANE4) + y4;
            const float4 wv = __ldg(&w4[k]);           // uniform per warp, L1-hot

            const float4 e0 = __ldg(p);
            const float4 e1 = __ldg(p + EY_PLANE4);
            const float4 e2 = __ldg(p + 2 * EY_PLANE4);
            const float4 e3 = __ldg(p + 3 * EY_PLANE4);

            acc.x += wv.x * e0.x + wv.y * e1.x + wv.z * e2.x + wv.w * e3.x;
            acc.y += wv.x * e0.y + wv.y * e1.y + wv.z * e2.y + wv.w * e3.y;
            acc.z += wv.x * e0.z + wv.y * e1.z + wv.z * e2.z + wv.w * e3.z;
            acc.w += wv.x * e0.w + wv.y * e1.w + wv.z * e2.w + wv.w * e3.w;
        }
    }

    if (active) {
        *reinterpret_cast<float4*>(out + (long)r * TOTAL + c) = acc;
    }
}

extern "C" void kernel_launch(void* const* d_in, const int* in_sizes, int n_in,
                              void* d_out, int out_size) {
    // Inputs (metadata order): hs (unused), U, neff, Ey
    const float* U    = (const float*)d_in[1];
    const float* neff = (const float*)d_in[2];
    const float* Ey   = (const float*)d_in[3];
    float* out = (float*)d_out;

    compute_weights_kernel<<<(NK * MODES + 255) / 256, 256>>>(U, neff);

    dim3 block(32, 8);
    dim3 grid((TOTAL + 127) / 128, TOTAL / 8);   // (10, 148)
    gather_en_kernel<<<grid, block>>>(Ey, out);
}